// round 1
// baseline (speedup 1.0000x reference)
#include <cuda_runtime.h>
#include <cstddef>

#define NB      65536
#define SEQL    5
#define HID     100
#define THREADS 256
#define WARPS   8

// Scratch for sub_mem between the two kernels (131 MB, static device array —
// allocation APIs are forbidden).
__device__ float g_submem[(size_t)NB * SEQL * HID];

// ---------------------------------------------------------------------------
// Packed fp32x2 FMA (sm_103a FFMA2) + 128-bit shared loads as two u64 pairs
// ---------------------------------------------------------------------------
__device__ __forceinline__ void fma2(unsigned long long& acc,
                                     unsigned long long a,
                                     unsigned long long b) {
    asm volatile("fma.rn.f32x2 %0, %1, %2, %0;" : "+l"(acc) : "l"(a), "l"(b));
}
__device__ __forceinline__ void lds2(unsigned long long& a,
                                     unsigned long long& b,
                                     unsigned addr) {
    asm volatile("ld.shared.v2.u64 {%0, %1}, [%2];"
                 : "=l"(a), "=l"(b) : "r"(addr));
}
__device__ __forceinline__ float2 unpack2(unsigned long long v) {
    float2 r;
    asm("mov.b64 {%0, %1}, %2;" : "=f"(r.x), "=f"(r.y) : "l"(v));
    return r;
}
__device__ __forceinline__ float tanh_fast(float x) {
    // tanh(x) = 1 - 2/(1+e^{2x}); MUFU-based, ~1e-6 rel err, saturates safely.
    float e = __expf(2.0f * x);
    return 1.0f - __fdividef(2.0f, 1.0f + e);
}
__device__ __forceinline__ float sigmoid_fast(float x) {
    return __fdividef(1.0f, 1.0f + __expf(-x));
}

// ---------------------------------------------------------------------------
// Kernel 1: mem_4att / sub_4att (tanh), attention, masked softmax, sub_mem
// Shared layout (floats):
//   [0,12800)            W_mem^T   128 rows x stride 100 (rows 100..127 = 0)
//   [12800,38912)        W_sub^T   128 rows x stride 204 (rows 100..127 = 0)
//   [38912,39040)        b_mem padded to 128 (tail = 0)
//   [39040,39168)        b_sub padded to 128 (tail = 0)
//   [39168, +8*1504)     per-warp stage: mem[0..499], cat(sub,raw)[500..1499]
// ---------------------------------------------------------------------------
#define K1_WTM   0
#define K1_WTS   12800
#define K1_BM    38912
#define K1_BS    39040
#define K1_STAGE 39168
#define K1_SMEM_FLOATS (K1_STAGE + WARPS * 1504)

__global__ void __launch_bounds__(THREADS, 1)
k1_attention(const float* __restrict__ sub_emb,
             const float* __restrict__ memory,
             const int*   __restrict__ sub_len,
             const float* __restrict__ sub_raw,
             const float* __restrict__ W_mem,
             const float* __restrict__ b_mem,
             const float* __restrict__ W_sub,
             const float* __restrict__ b_sub)
{
    extern __shared__ float smem[];
    const int tid = threadIdx.x;

    // Transposed weight loads (one-time per block; conflict pattern irrelevant)
    for (int idx = tid; idx < 100 * 100; idx += THREADS) {
        int k = idx / 100, j = idx - k * 100;
        smem[K1_WTM + j * 100 + k] = W_mem[idx];
    }
    for (int idx = tid; idx < 28 * 100; idx += THREADS)
        smem[K1_WTM + 100 * 100 + idx] = 0.f;
    for (int idx = tid; idx < 200 * 100; idx += THREADS) {
        int k = idx / 100, j = idx - k * 100;
        smem[K1_WTS + j * 204 + k] = W_sub[idx];
    }
    for (int idx = tid; idx < 28 * 204; idx += THREADS)
        smem[K1_WTS + 100 * 204 + idx] = 0.f;
    for (int idx = tid; idx < 128; idx += THREADS) {
        smem[K1_BM + idx] = (idx < 100) ? b_mem[idx] : 0.f;
        smem[K1_BS + idx] = (idx < 100) ? b_sub[idx] : 0.f;
    }
    __syncthreads();

    const int warp = tid >> 5, lane = tid & 31;
    const unsigned sbase = (unsigned)__cvta_generic_to_shared(smem);
    float* stf = smem + K1_STAGE + warp * 1504;
    const unsigned stq = sbase + (unsigned)(K1_STAGE + warp * 1504) * 4u;

    unsigned wm_addr[4], ws_addr[4];
#pragma unroll
    for (int t = 0; t < 4; ++t) {
        int j = lane + 32 * t;
        wm_addr[t] = sbase + (unsigned)(K1_WTM + j * 100) * 4u;
        ws_addr[t] = sbase + (unsigned)(K1_WTS + j * 204) * 4u;
    }

    const int gw = blockIdx.x * WARPS + warp;
    const int nw = gridDim.x * WARPS;

    for (int b = gw; b < NB; b += nw) {
        // stage inputs for this batch (warp-local)
        const float4* m4 = (const float4*)(memory  + (size_t)b * 500);
        const float4* s4 = (const float4*)(sub_emb + (size_t)b * 500);
        const float4* r4 = (const float4*)(sub_raw + (size_t)b * 500);
        for (int i = lane; i < 125; i += 32) {
            int e = i * 4; int r = e / 100; int k = e - r * 100;
            *(float4*)(stf + r * 100 + k)             = m4[i];
            *(float4*)(stf + 500 + r * 200 + k)       = s4[i];
            *(float4*)(stf + 500 + r * 200 + 100 + k) = r4[i];
        }
        const int slen = sub_len[b];
        __syncwarp();

        // ---- mem_4att = tanh(memory @ W_mem + b_mem) ----
        unsigned long long acc[5][4];
#pragma unroll
        for (int r = 0; r < 5; ++r)
#pragma unroll
            for (int t = 0; t < 4; ++t) acc[r][t] = 0ULL;

#pragma unroll 2
        for (int k = 0; k < 100; k += 4) {
            unsigned long long w0[4], w1[4], x0[5], x1[5];
#pragma unroll
            for (int t = 0; t < 4; ++t) lds2(w0[t], w1[t], wm_addr[t] + k * 4);
#pragma unroll
            for (int r = 0; r < 5; ++r) lds2(x0[r], x1[r], stq + (r * 100 + k) * 4);
#pragma unroll
            for (int r = 0; r < 5; ++r)
#pragma unroll
                for (int t = 0; t < 4; ++t) {
                    fma2(acc[r][t], x0[r], w0[t]);
                    fma2(acc[r][t], x1[r], w1[t]);
                }
        }
        float vm[5][4];
#pragma unroll
        for (int r = 0; r < 5; ++r)
#pragma unroll
            for (int t = 0; t < 4; ++t) {
                float2 p = unpack2(acc[r][t]);
                vm[r][t] = tanh_fast(p.x + p.y + smem[K1_BM + lane + 32 * t]);
            }

        // ---- sub_4att = tanh(cat(sub_emb, raw) @ W_sub + b_sub) ----
#pragma unroll
        for (int r = 0; r < 5; ++r)
#pragma unroll
            for (int t = 0; t < 4; ++t) acc[r][t] = 0ULL;

#pragma unroll 2
        for (int k = 0; k < 200; k += 4) {
            unsigned long long w0[4], w1[4], x0[5], x1[5];
#pragma unroll
            for (int t = 0; t < 4; ++t) lds2(w0[t], w1[t], ws_addr[t] + k * 4);
#pragma unroll
            for (int r = 0; r < 5; ++r)
                lds2(x0[r], x1[r], stq + (500 + r * 200 + k) * 4);
#pragma unroll
            for (int r = 0; r < 5; ++r)
#pragma unroll
                for (int t = 0; t < 4; ++t) {
                    fma2(acc[r][t], x0[r], w0[t]);
                    fma2(acc[r][t], x1[r], w1[t]);
                }
        }
        float vs[5][4];
#pragma unroll
        for (int r = 0; r < 5; ++r)
#pragma unroll
            for (int t = 0; t < 4; ++t) {
                float2 p = unpack2(acc[r][t]);
                vs[r][t] = tanh_fast(p.x + p.y + smem[K1_BS + lane + 32 * t]);
            }

        // ---- attention scores att[q][k'] = <sub4[q], mem4[k']> over H ----
        float att[5][5];
#pragma unroll
        for (int q = 0; q < 5; ++q)
#pragma unroll
            for (int kk = 0; kk < 5; ++kk) {
                float p = vs[q][0] * vm[kk][0];
                p = fmaf(vs[q][1], vm[kk][1], p);
                p = fmaf(vs[q][2], vm[kk][2], p);
                p = fmaf(vs[q][3], vm[kk][3], p);
                p += __shfl_xor_sync(0xffffffffu, p, 16);
                p += __shfl_xor_sync(0xffffffffu, p, 8);
                p += __shfl_xor_sync(0xffffffffu, p, 4);
                p += __shfl_xor_sync(0xffffffffu, p, 2);
                p += __shfl_xor_sync(0xffffffffu, p, 1);
                att[q][kk] = p;
            }

        // ---- masked softmax (mask is per-query-row; keys never masked) ----
        float wgt[5][5];
#pragma unroll
        for (int q = 0; q < 5; ++q) {
            if (q < slen) {
                float m = att[q][0];
#pragma unroll
                for (int kk = 1; kk < 5; ++kk) m = fmaxf(m, att[q][kk]);
                float e[5], s = 0.f;
#pragma unroll
                for (int kk = 0; kk < 5; ++kk) { e[kk] = __expf(att[q][kk] - m); s += e[kk]; }
                float inv = __fdividef(1.f, s);
#pragma unroll
                for (int kk = 0; kk < 5; ++kk) wgt[q][kk] = e[kk] * inv;
            } else {
#pragma unroll
                for (int kk = 0; kk < 5; ++kk) wgt[q][kk] = 0.f;
            }
        }

        // ---- sub_mem[q] = att[q] @ memory ----
        float mv[5][4];
#pragma unroll
        for (int kk = 0; kk < 5; ++kk)
#pragma unroll
            for (int t = 0; t < 4; ++t) {
                int j = lane + 32 * t;
                mv[kk][t] = (j < 100) ? stf[kk * 100 + j] : 0.f;
            }
        float* orow = g_submem + (size_t)b * 500;
#pragma unroll
        for (int q = 0; q < 5; ++q) {
            float sm0 = 0.f, sm1 = 0.f, sm2 = 0.f, sm3 = 0.f;
#pragma unroll
            for (int kk = 0; kk < 5; ++kk) {
                sm0 = fmaf(wgt[q][kk], mv[kk][0], sm0);
                sm1 = fmaf(wgt[q][kk], mv[kk][1], sm1);
                sm2 = fmaf(wgt[q][kk], mv[kk][2], sm2);
                sm3 = fmaf(wgt[q][kk], mv[kk][3], sm3);
            }
            orow[q * 100 + lane]      = sm0;
            orow[q * 100 + lane + 32] = sm1;
            orow[q * 100 + lane + 64] = sm2;
            if (lane < 4) orow[q * 100 + lane + 96] = sm3;
        }
        __syncwarp();   // protect stage vs next iteration
    }
}

// ---------------------------------------------------------------------------
// Kernel 2: g = sigmoid([sub_emb, sub_mem, sub_mem*sub_emb] @ W_gate + b);
//           out = (1-g)*sub_emb + g*sub_mem
// Shared layout (floats):
//   [0,38400)        W_gate^T 128 rows x stride 300 (rows 100..127 = 0)
//   [38400,38528)    b_gate padded to 128
//   [38528,+8*1504)  per-warp stage x[5][300] = [se | sm | se*sm]
// ---------------------------------------------------------------------------
#define K2_WTG   0
#define K2_BG    38400
#define K2_STAGE 38528
#define K2_SMEM_FLOATS (K2_STAGE + WARPS * 1504)

__global__ void __launch_bounds__(THREADS, 1)
k2_gate(const float* __restrict__ sub_emb,
        const float* __restrict__ W_gate,
        const float* __restrict__ b_gate,
        float* __restrict__ out)
{
    extern __shared__ float smem[];
    const int tid = threadIdx.x;

    for (int idx = tid; idx < 300 * 100; idx += THREADS) {
        int k = idx / 100, j = idx - k * 100;
        smem[K2_WTG + j * 300 + k] = W_gate[idx];
    }
    for (int idx = tid; idx < 28 * 300; idx += THREADS)
        smem[K2_WTG + 100 * 300 + idx] = 0.f;
    for (int idx = tid; idx < 128; idx += THREADS)
        smem[K2_BG + idx] = (idx < 100) ? b_gate[idx] : 0.f;
    __syncthreads();

    const int warp = tid >> 5, lane = tid & 31;
    const unsigned sbase = (unsigned)__cvta_generic_to_shared(smem);
    float* stf = smem + K2_STAGE + warp * 1504;
    const unsigned stq = sbase + (unsigned)(K2_STAGE + warp * 1504) * 4u;

    unsigned wg_addr[4];
#pragma unroll
    for (int t = 0; t < 4; ++t)
        wg_addr[t] = sbase + (unsigned)(K2_WTG + (lane + 32 * t) * 300) * 4u;

    const int gw = blockIdx.x * WARPS + warp;
    const int nw = gridDim.x * WARPS;

    for (int b = gw; b < NB; b += nw) {
        const float4* s4 = (const float4*)(sub_emb  + (size_t)b * 500);
        const float4* m4 = (const float4*)(g_submem + (size_t)b * 500);
        for (int i = lane; i < 125; i += 32) {
            int e = i * 4; int r = e / 100; int k = e - r * 100;
            float4 a = s4[i], c = m4[i];
            *(float4*)(stf + r * 300 + k)       = a;
            *(float4*)(stf + r * 300 + 100 + k) = c;
            float4 p = make_float4(a.x * c.x, a.y * c.y, a.z * c.z, a.w * c.w);
            *(float4*)(stf + r * 300 + 200 + k) = p;
        }
        __syncwarp();

        unsigned long long acc[5][4];
#pragma unroll
        for (int r = 0; r < 5; ++r)
#pragma unroll
            for (int t = 0; t < 4; ++t) acc[r][t] = 0ULL;

#pragma unroll 2
        for (int k = 0; k < 300; k += 4) {
            unsigned long long w0[4], w1[4], x0[5], x1[5];
#pragma unroll
            for (int t = 0; t < 4; ++t) lds2(w0[t], w1[t], wg_addr[t] + k * 4);
#pragma unroll
            for (int r = 0; r < 5; ++r) lds2(x0[r], x1[r], stq + (r * 300 + k) * 4);
#pragma unroll
            for (int r = 0; r < 5; ++r)
#pragma unroll
                for (int t = 0; t < 4; ++t) {
                    fma2(acc[r][t], x0[r], w0[t]);
                    fma2(acc[r][t], x1[r], w1[t]);
                }
        }

#pragma unroll
        for (int q = 0; q < 5; ++q)
#pragma unroll
            for (int t = 0; t < 4; ++t) {
                int j = lane + 32 * t;
                if (j < 100) {
                    float2 p = unpack2(acc[q][t]);
                    float z  = p.x + p.y + smem[K2_BG + j];
                    float g  = sigmoid_fast(z);
                    float se = stf[q * 300 + j];
                    float sm = stf[q * 300 + 100 + j];
                    out[(size_t)b * 500 + q * 100 + j] = fmaf(g, sm - se, se);
                }
            }
        __syncwarp();
    }
}

// ---------------------------------------------------------------------------
extern "C" void kernel_launch(void* const* d_in, const int* in_sizes, int n_in,
                              void* d_out, int out_size) {
    (void)in_sizes; (void)n_in; (void)out_size;
    const float* sub_emb = (const float*)d_in[0];
    const float* memory  = (const float*)d_in[1];
    const int*   sub_len = (const int*)  d_in[2];
    const float* sub_raw = (const float*)d_in[3];
    const float* W_mem   = (const float*)d_in[4];
    const float* b_mem   = (const float*)d_in[5];
    const float* W_sub   = (const float*)d_in[6];
    const float* b_sub   = (const float*)d_in[7];
    const float* W_gate  = (const float*)d_in[8];
    const float* b_gate  = (const float*)d_in[9];
    float* out = (float*)d_out;

    int sms = 148;
    cudaDeviceGetAttribute(&sms, cudaDevAttrMultiProcessorCount, 0);

    const size_t s1 = (size_t)K1_SMEM_FLOATS * sizeof(float);  // ~204.8 KB
    const size_t s2 = (size_t)K2_SMEM_FLOATS * sizeof(float);  // ~202.2 KB
    cudaFuncSetAttribute(k1_attention, cudaFuncAttributeMaxDynamicSharedMemorySize, (int)s1);
    cudaFuncSetAttribute(k2_gate,      cudaFuncAttributeMaxDynamicSharedMemorySize, (int)s2);

    k1_attention<<<sms, THREADS, s1>>>(sub_emb, memory, sub_len, sub_raw,
                                       W_mem, b_mem, W_sub, b_sub);
    k2_gate<<<sms, THREADS, s2>>>(sub_emb, W_gate, b_gate, out);
}

// round 5
// speedup vs baseline: 1.1995x; 1.1995x over previous
#include <cuda_runtime.h>
#include <cstddef>

#define NB      65536
#define SEQL    5
#define HID     100
#define THREADS 512
#define WARPS   16

// Scratch for sub_mem between the two kernels (131 MB, static device array —
// allocation APIs are forbidden).
__device__ float g_submem[(size_t)NB * SEQL * HID];

// ---------------------------------------------------------------------------
// Packed fp32x2 FMA (sm_103a FFMA2) + 128-bit shared loads as two u64 pairs
// ---------------------------------------------------------------------------
__device__ __forceinline__ void fma2(unsigned long long& acc,
                                     unsigned long long a,
                                     unsigned long long b) {
    asm volatile("fma.rn.f32x2 %0, %1, %2, %0;" : "+l"(acc) : "l"(a), "l"(b));
}
__device__ __forceinline__ void lds2(unsigned long long& a,
                                     unsigned long long& b,
                                     unsigned addr) {
    asm volatile("ld.shared.v2.u64 {%0, %1}, [%2];"
                 : "=l"(a), "=l"(b) : "r"(addr));
}
__device__ __forceinline__ float2 unpack2(unsigned long long v) {
    float2 r;
    asm("mov.b64 {%0, %1}, %2;" : "=f"(r.x), "=f"(r.y) : "l"(v));
    return r;
}
__device__ __forceinline__ float tanh_fast(float x) {
    float e = __expf(2.0f * x);
    return 1.0f - __fdividef(2.0f, 1.0f + e);
}
__device__ __forceinline__ float sigmoid_fast(float x) {
    return __fdividef(1.0f, 1.0f + __expf(-x));
}

// ---------------------------------------------------------------------------
// Kernel 1: mem_4att / sub_4att (tanh), attention, masked softmax, sub_mem
// Shared layout (floats):
//   [0,10000)            W_mem^T   100 rows x stride 100   (40.0 KB)
//   [10000,30400)        W_sub^T   100 rows x stride 204   (81.6 KB)
//   [30400,30504)        b_mem (100, +4 pad)
//   [30504,30608)        b_sub (100, +4 pad)
//   [30608,+16*1504)     per-warp stage: mem[0..499], cat(sub,raw)[500..1499]
// Total: 54,672 floats = 213.6 KiB  (< 227 KiB opt-in cap)
// Rows j>=100 of the padded output tile are computed on clamped addresses
// (garbage, never stored) instead of zero-padded weight rows.
// ---------------------------------------------------------------------------
#define K1_WTM   0
#define K1_WTS   10000
#define K1_BM    30400
#define K1_BS    30504
#define K1_STAGE 30608
#define K1_SMEM_FLOATS (K1_STAGE + WARPS * 1504)

__global__ void __launch_bounds__(THREADS, 1)
k1_attention(const float* __restrict__ sub_emb,
             const float* __restrict__ memory,
             const int*   __restrict__ sub_len,
             const float* __restrict__ sub_raw,
             const float* __restrict__ W_mem,
             const float* __restrict__ b_mem,
             const float* __restrict__ W_sub,
             const float* __restrict__ b_sub)
{
    extern __shared__ float smem[];
    const int tid = threadIdx.x;

    for (int idx = tid; idx < 100 * 100; idx += THREADS) {
        int k = idx / 100, j = idx - k * 100;
        smem[K1_WTM + j * 100 + k] = W_mem[idx];
    }
    for (int idx = tid; idx < 200 * 100; idx += THREADS) {
        int k = idx / 100, j = idx - k * 100;
        smem[K1_WTS + j * 204 + k] = W_sub[idx];
    }
    for (int idx = tid; idx < 100; idx += THREADS) {
        smem[K1_BM + idx] = b_mem[idx];
        smem[K1_BS + idx] = b_sub[idx];
    }
    __syncthreads();

    const int warp = tid >> 5, lane = tid & 31;
    const unsigned sbase = (unsigned)__cvta_generic_to_shared(smem);
    float* stf = smem + K1_STAGE + warp * 1504;
    const unsigned stq = sbase + (unsigned)(K1_STAGE + warp * 1504) * 4u;

    unsigned wm_addr[4], ws_addr[4];
    int jcl[4];
#pragma unroll
    for (int t = 0; t < 4; ++t) {
        int j = lane + 32 * t;
        jcl[t] = (j < 100) ? j : 99;           // clamp: replaces zero-pad rows
        wm_addr[t] = sbase + (unsigned)(K1_WTM + jcl[t] * 100) * 4u;
        ws_addr[t] = sbase + (unsigned)(K1_WTS + jcl[t] * 204) * 4u;
    }

    const int gw = blockIdx.x * WARPS + warp;
    const int nw = gridDim.x * WARPS;

    for (int b = gw; b < NB; b += nw) {
        const float4* m4 = (const float4*)(memory  + (size_t)b * 500);
        const float4* s4 = (const float4*)(sub_emb + (size_t)b * 500);
        const float4* r4 = (const float4*)(sub_raw + (size_t)b * 500);
        for (int i = lane; i < 125; i += 32) {
            int e = i * 4; int r = e / 100; int k = e - r * 100;
            *(float4*)(stf + r * 100 + k)             = m4[i];
            *(float4*)(stf + 500 + r * 200 + k)       = s4[i];
            *(float4*)(stf + 500 + r * 200 + 100 + k) = r4[i];
        }
        const int slen = sub_len[b];
        __syncwarp();

        // ---- mem_4att = tanh(memory @ W_mem + b_mem) ----
        unsigned long long acc[5][4];
#pragma unroll
        for (int r = 0; r < 5; ++r)
#pragma unroll
            for (int t = 0; t < 4; ++t) acc[r][t] = 0ULL;

#pragma unroll 2
        for (int k = 0; k < 100; k += 4) {
            unsigned long long w0[4], w1[4], x0[5], x1[5];
#pragma unroll
            for (int t = 0; t < 4; ++t) lds2(w0[t], w1[t], wm_addr[t] + k * 4);
#pragma unroll
            for (int r = 0; r < 5; ++r) lds2(x0[r], x1[r], stq + (r * 100 + k) * 4);
#pragma unroll
            for (int r = 0; r < 5; ++r)
#pragma unroll
                for (int t = 0; t < 4; ++t) {
                    fma2(acc[r][t], x0[r], w0[t]);
                    fma2(acc[r][t], x1[r], w1[t]);
                }
        }
        float vm[5][4];
#pragma unroll
        for (int r = 0; r < 5; ++r)
#pragma unroll
            for (int t = 0; t < 4; ++t) {
                float2 p = unpack2(acc[r][t]);
                vm[r][t] = tanh_fast(p.x + p.y + smem[K1_BM + jcl[t]]);
            }

        // ---- sub_4att = tanh(cat(sub_emb, raw) @ W_sub + b_sub) ----
#pragma unroll
        for (int r = 0; r < 5; ++r)
#pragma unroll
            for (int t = 0; t < 4; ++t) acc[r][t] = 0ULL;

#pragma unroll 2
        for (int k = 0; k < 200; k += 4) {
            unsigned long long w0[4], w1[4], x0[5], x1[5];
#pragma unroll
            for (int t = 0; t < 4; ++t) lds2(w0[t], w1[t], ws_addr[t] + k * 4);
#pragma unroll
            for (int r = 0; r < 5; ++r)
                lds2(x0[r], x1[r], stq + (500 + r * 200 + k) * 4);
#pragma unroll
            for (int r = 0; r < 5; ++r)
#pragma unroll
                for (int t = 0; t < 4; ++t) {
                    fma2(acc[r][t], x0[r], w0[t]);
                    fma2(acc[r][t], x1[r], w1[t]);
                }
        }
        float vs[5][4];
#pragma unroll
        for (int r = 0; r < 5; ++r)
#pragma unroll
            for (int t = 0; t < 4; ++t) {
                float2 p = unpack2(acc[r][t]);
                vs[r][t] = tanh_fast(p.x + p.y + smem[K1_BS + jcl[t]]);
            }

        // zero out clamped lanes so attention dot products are exact
#pragma unroll
        for (int r = 0; r < 5; ++r) {
            if (lane + 96 >= 100) { vm[r][3] = 0.f; vs[r][3] = 0.f; }
        }

        // ---- attention scores att[q][k'] = <sub4[q], mem4[k']> over H ----
        float att[5][5];
#pragma unroll
        for (int q = 0; q < 5; ++q)
#pragma unroll
            for (int kk = 0; kk < 5; ++kk) {
                float p = vs[q][0] * vm[kk][0];
                p = fmaf(vs[q][1], vm[kk][1], p);
                p = fmaf(vs[q][2], vm[kk][2], p);
                p = fmaf(vs[q][3], vm[kk][3], p);
                p += __shfl_xor_sync(0xffffffffu, p, 16);
                p += __shfl_xor_sync(0xffffffffu, p, 8);
                p += __shfl_xor_sync(0xffffffffu, p, 4);
                p += __shfl_xor_sync(0xffffffffu, p, 2);
                p += __shfl_xor_sync(0xffffffffu, p, 1);
                att[q][kk] = p;
            }

        // ---- masked softmax (per-query-row mask; keys never masked) ----
        float wgt[5][5];
#pragma unroll
        for (int q = 0; q < 5; ++q) {
            if (q < slen) {
                float m = att[q][0];
#pragma unroll
                for (int kk = 1; kk < 5; ++kk) m = fmaxf(m, att[q][kk]);
                float e[5], s = 0.f;
#pragma unroll
                for (int kk = 0; kk < 5; ++kk) { e[kk] = __expf(att[q][kk] - m); s += e[kk]; }
                float inv = __fdividef(1.f, s);
#pragma unroll
                for (int kk = 0; kk < 5; ++kk) wgt[q][kk] = e[kk] * inv;
            } else {
#pragma unroll
                for (int kk = 0; kk < 5; ++kk) wgt[q][kk] = 0.f;
            }
        }

        // ---- sub_mem[q] = att[q] @ memory ----
        float mv[5][4];
#pragma unroll
        for (int kk = 0; kk < 5; ++kk)
#pragma unroll
            for (int t = 0; t < 4; ++t) {
                int j = lane + 32 * t;
                mv[kk][t] = (j < 100) ? stf[kk * 100 + j] : 0.f;
            }
        float* orow = g_submem + (size_t)b * 500;
#pragma unroll
        for (int q = 0; q < 5; ++q) {
            float sm0 = 0.f, sm1 = 0.f, sm2 = 0.f, sm3 = 0.f;
#pragma unroll
            for (int kk = 0; kk < 5; ++kk) {
                sm0 = fmaf(wgt[q][kk], mv[kk][0], sm0);
                sm1 = fmaf(wgt[q][kk], mv[kk][1], sm1);
                sm2 = fmaf(wgt[q][kk], mv[kk][2], sm2);
                sm3 = fmaf(wgt[q][kk], mv[kk][3], sm3);
            }
            orow[q * 100 + lane]      = sm0;
            orow[q * 100 + lane + 32] = sm1;
            orow[q * 100 + lane + 64] = sm2;
            if (lane < 4) orow[q * 100 + lane + 96] = sm3;
        }
        __syncwarp();   // protect stage vs next iteration
    }
}

// ---------------------------------------------------------------------------
// Kernel 2: g = sigmoid([sub_emb, sub_mem, sub_mem*sub_emb] @ W_gate + b);
//           out = (1-g)*sub_emb + g*sub_mem
// Shared layout (floats):
//   [0,30000)        W_gate^T 100 rows x stride 300 (120 KB)
//   [30000,30104)    b_gate (100, +4 pad)
//   [30104,+16*1512) per-warp stage x[5][300] = [se | sm | se*sm], stride 1512
// Total: 54,296 floats = 212.1 KiB
// ---------------------------------------------------------------------------
#define K2_WTG   0
#define K2_BG    30000
#define K2_STAGE 30104
#define K2_SMEM_FLOATS (K2_STAGE + WARPS * 1512)

__global__ void __launch_bounds__(THREADS, 1)
k2_gate(const float* __restrict__ sub_emb,
        const float* __restrict__ W_gate,
        const float* __restrict__ b_gate,
        float* __restrict__ out)
{
    extern __shared__ float smem[];
    const int tid = threadIdx.x;

    for (int idx = tid; idx < 300 * 100; idx += THREADS) {
        int k = idx / 100, j = idx - k * 100;
        smem[K2_WTG + j * 300 + k] = W_gate[idx];
    }
    for (int idx = tid; idx < 100; idx += THREADS)
        smem[K2_BG + idx] = b_gate[idx];
    __syncthreads();

    const int warp = tid >> 5, lane = tid & 31;
    const unsigned sbase = (unsigned)__cvta_generic_to_shared(smem);
    float* stf = smem + K2_STAGE + warp * 1512;
    const unsigned stq = sbase + (unsigned)(K2_STAGE + warp * 1512) * 4u;

    unsigned wg_addr[4];
    int jcl[4];
#pragma unroll
    for (int t = 0; t < 4; ++t) {
        int j = lane + 32 * t;
        jcl[t] = (j < 100) ? j : 99;
        wg_addr[t] = sbase + (unsigned)(K2_WTG + jcl[t] * 300) * 4u;
    }

    const int gw = blockIdx.x * WARPS + warp;
    const int nw = gridDim.x * WARPS;

    for (int b = gw; b < NB; b += nw) {
        const float4* s4 = (const float4*)(sub_emb  + (size_t)b * 500);
        const float4* m4 = (const float4*)(g_submem + (size_t)b * 500);
        for (int i = lane; i < 125; i += 32) {
            int e = i * 4; int r = e / 100; int k = e - r * 100;
            float4 a = s4[i], c = m4[i];
            *(float4*)(stf + r * 300 + k)       = a;
            *(float4*)(stf + r * 300 + 100 + k) = c;
            float4 p = make_float4(a.x * c.x, a.y * c.y, a.z * c.z, a.w * c.w);
            *(float4*)(stf + r * 300 + 200 + k) = p;
        }
        __syncwarp();

        unsigned long long acc[5][4];
#pragma unroll
        for (int r = 0; r < 5; ++r)
#pragma unroll
            for (int t = 0; t < 4; ++t) acc[r][t] = 0ULL;

#pragma unroll 2
        for (int k = 0; k < 300; k += 4) {
            unsigned long long w0[4], w1[4], x0[5], x1[5];
#pragma unroll
            for (int t = 0; t < 4; ++t) lds2(w0[t], w1[t], wg_addr[t] + k * 4);
#pragma unroll
            for (int r = 0; r < 5; ++r) lds2(x0[r], x1[r], stq + (r * 300 + k) * 4);
#pragma unroll
            for (int r = 0; r < 5; ++r)
#pragma unroll
                for (int t = 0; t < 4; ++t) {
                    fma2(acc[r][t], x0[r], w0[t]);
                    fma2(acc[r][t], x1[r], w1[t]);
                }
        }

#pragma unroll
        for (int q = 0; q < 5; ++q)
#pragma unroll
            for (int t = 0; t < 4; ++t) {
                int j = lane + 32 * t;
                if (j < 100) {
                    float2 p = unpack2(acc[q][t]);
                    float z  = p.x + p.y + smem[K2_BG + j];
                    float g  = sigmoid_fast(z);
                    float se = stf[q * 300 + j];
                    float sm = stf[q * 300 + 100 + j];
                    out[(size_t)b * 500 + q * 100 + j] = fmaf(g, sm - se, se);
                }
            }
        __syncwarp();
    }
}

// ---------------------------------------------------------------------------
extern "C" void kernel_launch(void* const* d_in, const int* in_sizes, int n_in,
                              void* d_out, int out_size) {
    (void)in_sizes; (void)n_in; (void)out_size;
    const float* sub_emb = (const float*)d_in[0];
    const float* memory  = (const float*)d_in[1];
    const int*   sub_len = (const int*)  d_in[2];
    const float* sub_raw = (const float*)d_in[3];
    const float* W_mem   = (const float*)d_in[4];
    const float* b_mem   = (const float*)d_in[5];
    const float* W_sub   = (const float*)d_in[6];
    const float* b_sub   = (const float*)d_in[7];
    const float* W_gate  = (const float*)d_in[8];
    const float* b_gate  = (const float*)d_in[9];
    float* out = (float*)d_out;

    int sms = 148;
    cudaDeviceGetAttribute(&sms, cudaDevAttrMultiProcessorCount, 0);

    const size_t s1 = (size_t)K1_SMEM_FLOATS * sizeof(float);  // 213.6 KiB
    const size_t s2 = (size_t)K2_SMEM_FLOATS * sizeof(float);  // 212.1 KiB
    cudaFuncSetAttribute(k1_attention, cudaFuncAttributeMaxDynamicSharedMemorySize, (int)s1);
    cudaFuncSetAttribute(k2_gate,      cudaFuncAttributeMaxDynamicSharedMemorySize, (int)s2);

    k1_attention<<<sms, THREADS, s1>>>(sub_emb, memory, sub_len, sub_raw,
                                       W_mem, b_mem, W_sub, b_sub);
    k2_gate<<<sms, THREADS, s2>>>(sub_emb, W_gate, b_gate, out);
}